// round 8
// baseline (speedup 1.0000x reference)
#include <cuda_runtime.h>
#include <cstdint>
#include <cstddef>

// MHA forward: B=2, S=2048, D_MODEL=1024, H=16, DK=64
// Outputs: out [2,2048,1024] then attn [2,16,2048,2048] (fp32, concatenated).
// tf32 mma.sync; q/k/v pre-rounded to tf32 at projection epilogue.
// k_attn: SINGLE pass — QK once, PV (unnormalized) on live chunks only,
// raw e written to attn then scaled in-place from L2 after rowsum is known.

#define QK_SCALE 0.125f
#define UNIF 0.00048828125f   // 1/2048, exact power of two

// ---------------- device scratch ----------------
__device__ __align__(256) float g_q[2 * 16 * 2048 * 64];
__device__ __align__(256) float g_k[2 * 16 * 2048 * 64];
__device__ __align__(256) float g_v[2 * 16 * 2048 * 64];
__device__ __align__(256) float g_ctx[4096 * 1024];
__device__ __align__(256) float g_vsum[32 * 64];     // per (b,h): colsum of V
__device__ __align__(256) unsigned char g_mask[4096];
__device__ __align__(256) float g_attn[134217728];   // fallback

// ---------------- helpers ----------------
__device__ __forceinline__ float t32(float x) {
    unsigned u;
    asm("cvt.rna.tf32.f32 %0, %1;" : "=r"(u) : "f"(x));
    return __uint_as_float(u);
}

__device__ __forceinline__ void mma8(float c[4], const unsigned a[4], const unsigned b[2]) {
    asm volatile("mma.sync.aligned.m16n8k8.row.col.f32.tf32.tf32.f32 "
                 "{%0,%1,%2,%3},{%4,%5,%6,%7},{%8,%9},{%0,%1,%2,%3};"
                 : "+f"(c[0]), "+f"(c[1]), "+f"(c[2]), "+f"(c[3])
                 : "r"(a[0]), "r"(a[1]), "r"(a[2]), "r"(a[3]),
                   "r"(b[0]), "r"(b[1]));
}

__device__ __forceinline__ unsigned s2u(const void* p) {
    return (unsigned)__cvta_generic_to_shared(p);
}
__device__ __forceinline__ void cpa16(unsigned dst, const void* src) {
    asm volatile("cp.async.cg.shared.global [%0], [%1], 16;" :: "r"(dst), "l"(src));
}
__device__ __forceinline__ void cpa_commit() {
    asm volatile("cp.async.commit_group;" ::: "memory");
}
template<int N> __device__ __forceinline__ void cpa_wait() {
    asm volatile("cp.async.wait_group %0;" :: "n"(N) : "memory");
}

// copy 128x64-float tile (row stride 64 gmem) to smem (row stride 68), 512 thr
__device__ __forceinline__ void cp_tile512(float* dstbase, const float* src, int tid) {
#pragma unroll
    for (int j = 0; j < 4; j++) {
        const int i = tid + 512 * j;
        const int r = i >> 4, c = (i & 15) << 2;
        cpa16(s2u(dstbase + r * 68 + c), src + r * 64 + c);
    }
}

// ---------------- mask dtype detection + canonicalization ----------------
__global__ void k_mask(const unsigned int* __restrict__ raw)
{
    __shared__ int flags[4];
    __shared__ int mode;
    const int tid = threadIdx.x;
    if (tid < 4) flags[tid] = 0;
    __syncthreads();
    unsigned int w = raw[tid];
    if (w > 1u) flags[0] = 1;
    if (w == 1u) flags[1] = 1;
    if (w != 0u && w != 0x3F800000u) flags[2] = 1;
    if (w == 0x3F800000u) flags[3] = 1;
    __syncthreads();
    if (tid == 0) {
        if (!flags[0] && flags[1])      mode = 0;
        else if (!flags[2] && flags[3]) mode = 1;
        else                            mode = 2;
    }
    __syncthreads();
    const int md = mode;
    for (int i = tid; i < 4096; i += 1024) {
        unsigned char v;
        if (md == 0)      v = (unsigned char)(((const int*)raw)[i] != 0);
        else if (md == 1) v = (unsigned char)(((const float*)raw)[i] != 0.0f);
        else              v = (unsigned char)(((const unsigned char*)raw)[i] != 0);
        g_mask[i] = v;
    }
}

// ---------------- vsum: g_vsum[bh][d] = sum_k V[bh][k][d] ----------------
__global__ void k_vsum()
{
    __shared__ float part[4][64];
    const int bh = blockIdx.x;
    const int d = threadIdx.x & 63, j = threadIdx.x >> 6;
    const float* Vp = g_v + (size_t)bh * 2048 * 64;
    float s = 0.0f;
    for (int k = j; k < 2048; k += 4) s += Vp[(size_t)k * 64 + d];
    part[j][d] = s;
    __syncthreads();
    if (threadIdx.x < 64)
        g_vsum[bh * 64 + threadIdx.x] = part[0][threadIdx.x] + part[1][threadIdx.x]
                                      + part[2][threadIdx.x] + part[3][threadIdx.x];
}

// ============ GEMM core: C = A @ W^T + bias, M=4096,N=1024,K=1024 ========
extern __shared__ float smem_dyn[];

template<int ROUND_SCATTER>
__device__ __forceinline__ void gemm_body(
    const float* __restrict__ A, const float* __restrict__ W,
    const float* __restrict__ bias, float* __restrict__ tgt)
{
    const int tid = threadIdx.x;
    const int bm = blockIdx.y * 128;
    const int bn = blockIdx.x * 128;
    const int w = tid >> 5, lane = tid & 31;
    const int g = lane >> 2, t = lane & 3;
    const int wm = (w >> 2) * 64, wn = (w & 3) * 32;
    const int lr = tid >> 1, lk = (tid & 1) * 8;
    const float* Ap = A + (size_t)(bm + lr) * 1024 + lk;
    const float* Wp = W + (size_t)(bn + lr) * 1024 + lk;

    float acc[4][4][4];
#pragma unroll
    for (int mt = 0; mt < 4; mt++)
#pragma unroll
        for (int nt = 0; nt < 4; nt++)
#pragma unroll
            for (int i = 0; i < 4; i++) acc[mt][nt][i] = 0.0f;

    float4 ra0, ra1, rw0, rw1;
    ra0 = *(const float4*)(Ap);     ra1 = *(const float4*)(Ap + 4);
    rw0 = *(const float4*)(Wp);     rw1 = *(const float4*)(Wp + 4);
    {
        float* pa = smem_dyn + lr * 20 + lk;
        float* pw = smem_dyn + 5120 + lr * 20 + lk;
        float4 ta = make_float4(t32(ra0.x), t32(ra0.y), t32(ra0.z), t32(ra0.w));
        float4 tb = make_float4(t32(ra1.x), t32(ra1.y), t32(ra1.z), t32(ra1.w));
        *(float4*)pa = ta; *(float4*)(pa + 4) = tb;
        ta = make_float4(t32(rw0.x), t32(rw0.y), t32(rw0.z), t32(rw0.w));
        tb = make_float4(t32(rw1.x), t32(rw1.y), t32(rw1.z), t32(rw1.w));
        *(float4*)pw = ta; *(float4*)(pw + 4) = tb;
    }
    __syncthreads();

    for (int kc = 0; kc < 64; kc++) {
        const int s = kc & 1;
        if (kc < 63) {
            const int off = (kc + 1) * 16;
            ra0 = *(const float4*)(Ap + off);     ra1 = *(const float4*)(Ap + off + 4);
            rw0 = *(const float4*)(Wp + off);     rw1 = *(const float4*)(Wp + off + 4);
        }
        const float* As = smem_dyn + s * 2560;
        const float* Ws = smem_dyn + 5120 + s * 2560;
#pragma unroll
        for (int kk = 0; kk < 2; kk++) {
            unsigned af[4][4], bf[4][2];
#pragma unroll
            for (int mt = 0; mt < 4; mt++) {
                const float* p = As + (wm + mt * 16 + g) * 20 + kk * 8 + t;
                af[mt][0] = __float_as_uint(p[0]);
                af[mt][1] = __float_as_uint(p[8 * 20]);
                af[mt][2] = __float_as_uint(p[4]);
                af[mt][3] = __float_as_uint(p[8 * 20 + 4]);
            }
#pragma unroll
            for (int nt = 0; nt < 4; nt++) {
                const float* p = Ws + (wn + nt * 8 + g) * 20 + kk * 8 + t;
                bf[nt][0] = __float_as_uint(p[0]);
                bf[nt][1] = __float_as_uint(p[4]);
            }
#pragma unroll
            for (int mt = 0; mt < 4; mt++)
#pragma unroll
                for (int nt = 0; nt < 4; nt++)
                    mma8(acc[mt][nt], af[mt], bf[nt]);
        }
        if (kc < 63) {
            const int s2 = (kc + 1) & 1;
            float* pa = smem_dyn + s2 * 2560 + lr * 20 + lk;
            float* pw = smem_dyn + 5120 + s2 * 2560 + lr * 20 + lk;
            float4 ta = make_float4(t32(ra0.x), t32(ra0.y), t32(ra0.z), t32(ra0.w));
            float4 tb = make_float4(t32(ra1.x), t32(ra1.y), t32(ra1.z), t32(ra1.w));
            *(float4*)pa = ta; *(float4*)(pa + 4) = tb;
            ta = make_float4(t32(rw0.x), t32(rw0.y), t32(rw0.z), t32(rw0.w));
            tb = make_float4(t32(rw1.x), t32(rw1.y), t32(rw1.z), t32(rw1.w));
            *(float4*)pw = ta; *(float4*)(pw + 4) = tb;
        }
        __syncthreads();
    }

#pragma unroll
    for (int mt = 0; mt < 4; mt++) {
#pragma unroll
        for (int nt = 0; nt < 4; nt++) {
            const int c0 = bn + wn + nt * 8 + 2 * t;
            const float b0v = bias[c0], b1v = bias[c0 + 1];
#pragma unroll
            for (int half = 0; half < 2; half++) {
                const int m = bm + wm + mt * 16 + g + half * 8;
                float v0 = acc[mt][nt][half * 2 + 0] + b0v;
                float v1 = acc[mt][nt][half * 2 + 1] + b1v;
                if (ROUND_SCATTER) {
                    v0 = t32(v0); v1 = t32(v1);
                    const int b = m >> 11, sr = m & 2047;
                    const int h = c0 >> 6, d = c0 & 63;
                    float* dst = tgt + (((size_t)((b << 4) + h)) * 2048 + sr) * 64 + d;
                    dst[0] = v0; dst[1] = v1;
                } else {
                    float* dst = tgt + (size_t)m * 1024 + c0;
                    dst[0] = v0; dst[1] = v1;
                }
            }
        }
    }
}

__global__ __launch_bounds__(256, 2) void k_proj(
    const float* __restrict__ A0, const float* __restrict__ A1, const float* __restrict__ A2,
    const float* __restrict__ W0, const float* __restrict__ W1, const float* __restrict__ W2,
    const float* __restrict__ b0, const float* __restrict__ b1, const float* __restrict__ b2)
{
    const int z = blockIdx.z;
    const float* A = (z == 0) ? A0 : (z == 1) ? A1 : A2;
    const float* W = (z == 0) ? W0 : (z == 1) ? W1 : W2;
    const float* b = (z == 0) ? b0 : (z == 1) ? b1 : b2;
    float* tgt = (z == 0) ? g_q : (z == 1) ? g_k : g_v;
    gemm_body<1>(A, W, b, tgt);
}

__global__ __launch_bounds__(256, 2) void k_out(
    const float* __restrict__ W, const float* __restrict__ b, float* __restrict__ out)
{
    gemm_body<0>(g_ctx, W, b, out);
}

// ============ fused attention core, single pass, 512 threads =============
// smem float layout:
//  Qs 0 (8704), Ks[2] 8704/17408, Vs 26112 (8704), Ps 34816 (16896 = 128x132),
//  rowsum 51712, rinv 51840, runi 51968(int), Ms @ float 52096 (2048 B)
__global__ __launch_bounds__(512) void k_attn(float* __restrict__ dattn, int use_dout)
{
    float* Qs = smem_dyn;
    float* Vs = smem_dyn + 26112;
    float* Ps = smem_dyn + 34816;
    float* rowsum = smem_dyn + 51712;
    float* rinv   = smem_dyn + 51840;
    int*   runi   = (int*)(smem_dyn + 51968);
    unsigned char* Ms = (unsigned char*)(smem_dyn + 52096);

    float* attn = use_dout ? dattn : g_attn;
    const int tid = threadIdx.x;
    const int bh = blockIdx.y;
    const int bb = bh >> 4, hh = bh & 15;
    const int x = blockIdx.x;          // q-tile index
    const int q0 = x * 128;
    const float* Qp = g_q + (size_t)bh * 2048 * 64;
    const float* Kp = g_k + (size_t)bh * 2048 * 64;
    const float* Vp = g_v + (size_t)bh * 2048 * 64;

    const int w = tid >> 5, lane = tid & 31;
    const int g = lane >> 2, t = lane & 3;
    const int wmS = (w >> 2) * 32, wnS = (w & 3) * 32;   // scores 4x4, warp tile 32x32
    const int wmO = (w >> 1) * 16, wnO = (w & 1) * 32;   // PV 8x2, warp tile 16x32

    // ---- init + prologue (one group: Qs, Ks(0), mask) ----
    if (tid < 128) rowsum[tid] = 0.0f;
    cp_tile512(Qs, Qp + (size_t)q0 * 64, tid);
    cp_tile512(smem_dyn + 8704, Kp, tid);
    if (tid < 128)
        cpa16(s2u(Ms + tid * 16), g_mask + bb * 2048 + tid * 16);
    cpa_commit();

    float rs[2][2];
    rs[0][0] = rs[0][1] = rs[1][0] = rs[1][1] = 0.0f;
    float oacc[4][4];
#pragma unroll
    for (int nt = 0; nt < 4; nt++)
#pragma unroll
        for (int i = 0; i < 4; i++) oacc[nt][i] = 0.0f;

    // ---- single pass over live chunks ----
    for (int kc = 0; kc <= x; kc++) {
        const int kc0 = kc * 128;
        cpa_wait<0>();            // Ks(kc) ready (drains all pending)
        __syncthreads();          // prior Vs/Ps consumers done
        cp_tile512(Vs, Vp + (size_t)kc0 * 64, tid);
        cpa_commit();             // group A (Vs)
        if (kc < x) {
            cp_tile512(smem_dyn + 8704 + ((kc + 1) & 1) * 8704,
                       Kp + (size_t)(kc + 1) * 128 * 64, tid);
        }
        cpa_commit();             // group B — always committed (may be empty)
        const float* Kb = smem_dyn + 8704 + (kc & 1) * 8704;

        // QK mma
        float acc[2][4][4];
#pragma unroll
        for (int mt = 0; mt < 2; mt++)
#pragma unroll
            for (int nt = 0; nt < 4; nt++)
#pragma unroll
                for (int i = 0; i < 4; i++) acc[mt][nt][i] = 0.0f;
#pragma unroll
        for (int kk = 0; kk < 8; kk++) {
            unsigned af[2][4], bf[4][2];
#pragma unroll
            for (int mt = 0; mt < 2; mt++) {
                const float* p = Qs + (wmS + mt * 16 + g) * 68 + kk * 8 + t;
                af[mt][0] = __float_as_uint(p[0]);
                af[mt][1] = __float_as_uint(p[8 * 68]);
                af[mt][2] = __float_as_uint(p[4]);
                af[mt][3] = __float_as_uint(p[8 * 68 + 4]);
            }
#pragma unroll
            for (int nt = 0; nt < 4; nt++) {
                const float* p = Kb + (wnS + nt * 8 + g) * 68 + kk * 8 + t;
                bf[nt][0] = __float_as_uint(p[0]);
                bf[nt][1] = __float_as_uint(p[4]);
            }
#pragma unroll
            for (int mt = 0; mt < 2; mt++)
#pragma unroll
                for (int nt = 0; nt < 4; nt++)
                    mma8(acc[mt][nt], af[mt], bf[nt]);
        }

        // epilogue: e = exp(masked s) (UNNORMALIZED); rowsum accumulate; Ps <- e
#pragma unroll
        for (int mt = 0; mt < 2; mt++) {
#pragma unroll
            for (int half = 0; half < 2; half++) {
                const int rl = wmS + mt * 16 + g + 8 * half;
                const int rq = q0 + rl;
#pragma unroll
                for (int nt = 0; nt < 4; nt++) {
                    const int cl = wnS + nt * 8 + 2 * t;
                    const int c0 = kc0 + cl;
                    const unsigned char mk0 = Ms[c0], mk1 = Ms[c0 + 1];
                    const float s0 = acc[mt][nt][half*2+0] * QK_SCALE;
                    const float s1 = acc[mt][nt][half*2+1] * QK_SCALE;
                    float e0 = (!mk0 || c0 > rq)     ? 0.0f : __expf(s0);
                    float e1 = (!mk1 || c0 + 1 > rq) ? 0.0f : __expf(s1);
                    rs[mt][half] += e0 + e1;
                    *(float2*)(Ps + rl * 132 + cl) = make_float2(e0, e1);
                }
            }
        }
        cpa_wait<1>();            // drain group A (Vs); group B (next Ks) may pend
        __syncthreads();          // Ps + Vs visible to all

        // write RAW e to attn (coalesced); scaled in place later from L2
#pragma unroll
        for (int u = 0; u < 8; u++) {
            const int f = tid + 512 * u;
            const int r = f >> 5, c = (f & 31) * 4;
            float4 v = *(const float4*)(Ps + r * 132 + c);
            *(float4*)(attn + ((size_t)(bh * 2048 + q0 + r)) * 2048 + kc0 + c) = v;
        }

        // PV mma with unnormalized e: oacc += t32(Ps) @ Vs  (warp tile 16x32)
#pragma unroll
        for (int kk = 0; kk < 16; kk++) {
            unsigned af[4], bf[4][2];
            {
                const float* p = Ps + (wmO + g) * 132 + kk * 8 + t;
                af[0] = __float_as_uint(t32(p[0]));
                af[1] = __float_as_uint(t32(p[8 * 132]));
                af[2] = __float_as_uint(t32(p[4]));
                af[3] = __float_as_uint(t32(p[8 * 132 + 4]));
            }
#pragma unroll
            for (int nt = 0; nt < 4; nt++) {
                const float* p = Vs + (kk * 8 + t) * 68 + wnO + nt * 8 + g;
                bf[nt][0] = __float_as_uint(p[0]);
                bf[nt][1] = __float_as_uint(p[4 * 68]);
            }
#pragma unroll
            for (int nt = 0; nt < 4; nt++)
                mma8(oacc[nt], af, bf[nt]);
        }
    }

    // ---- rowsum reduce -> rinv / runi ----
#pragma unroll
    for (int mt = 0; mt < 2; mt++)
#pragma unroll
        for (int half = 0; half < 2; half++) {
            float v = rs[mt][half];
            v += __shfl_xor_sync(0xffffffffu, v, 1);
            v += __shfl_xor_sync(0xffffffffu, v, 2);
            if (t == 0) atomicAdd(&rowsum[wmS + mt * 16 + g + 8 * half], v);
        }
    __syncthreads();
    if (tid < 128) {
        const float s = rowsum[tid];
        if (s == 0.0f) { runi[tid] = 1; rinv[tid] = 0.0f; }
        else           { runi[tid] = 0; rinv[tid] = 1.0f / s; }
    }
    __syncthreads();

    // ---- scale phase: normalize raw attn in place (L2-hot), fill dead ----
    for (int kc = 0; kc < 16; kc++) {
        const int kc0 = kc * 128;
        const bool live = (kc <= x);
#pragma unroll
        for (int u = 0; u < 8; u++) {
            const int f = tid + 512 * u;
            const int r = f >> 5, c = (f & 31) * 4;
            float* addr = attn + ((size_t)(bh * 2048 + q0 + r)) * 2048 + kc0 + c;
            float4 v;
            if (runi[r]) {
                v = make_float4(UNIF, UNIF, UNIF, UNIF);
            } else if (live) {
                const float ri = rinv[r];
                v = *(const float4*)addr;
                v.x *= ri; v.y *= ri; v.z *= ri; v.w *= ri;
            } else {
                v = make_float4(0.f, 0.f, 0.f, 0.f);
            }
            *(float4*)addr = v;
        }
    }

    // ---- finalize oacc: scale by rinv; uniform rows -> UNIF * vsum ----
#pragma unroll
    for (int nt = 0; nt < 4; nt++) {
        const int d0 = wnO + nt * 8 + 2 * t;
#pragma unroll
        for (int half = 0; half < 2; half++) {
            const int rl = wmO + g + half * 8;
            const int rq = q0 + rl;
            float v0, v1;
            if (runi[rl]) {
                v0 = UNIF * g_vsum[bh * 64 + d0];
                v1 = UNIF * g_vsum[bh * 64 + d0 + 1];
            } else {
                const float ri = rinv[rl];
                v0 = oacc[nt][half*2+0] * ri;
                v1 = oacc[nt][half*2+1] * ri;
            }
            *(float2*)(g_ctx + ((size_t)(bb * 2048 + rq)) * 1024 + hh * 64 + d0)
                = make_float2(v0, v1);
        }
    }
}

// ---------------- launch ----------------
extern "C" void kernel_launch(void* const* d_in, const int* in_sizes, int n_in,
                              void* d_out, int out_size)
{
    const float* q_in = (const float*)d_in[0];
    const float* k_in = (const float*)d_in[1];
    const float* v_in = (const float*)d_in[2];
    const void*  mask = d_in[3];
    const float* Wq = (const float*)d_in[4];  const float* bq = (const float*)d_in[5];
    const float* Wk = (const float*)d_in[6];  const float* bk = (const float*)d_in[7];
    const float* Wv = (const float*)d_in[8];  const float* bv = (const float*)d_in[9];
    const float* Wo = (const float*)d_in[10]; const float* bo = (const float*)d_in[11];
    float* out = (float*)d_out;

    const int use_dout = (out_size >= 4194304 + 134217728) ? 1 : 0;
    float* dattn = out + 4194304;

    const int SM_G = 10240 * 4;               // 40 KB
    const int SM_A = (52100 + 512) * 4;       // ~205.5 KB
    cudaFuncSetAttribute(k_proj, cudaFuncAttributeMaxDynamicSharedMemorySize, SM_G);
    cudaFuncSetAttribute(k_out,  cudaFuncAttributeMaxDynamicSharedMemorySize, SM_G);
    cudaFuncSetAttribute(k_attn, cudaFuncAttributeMaxDynamicSharedMemorySize, SM_A);

    k_mask<<<1, 1024>>>((const unsigned int*)mask);

    k_proj<<<dim3(8, 32, 3), 256, SM_G>>>(q_in, k_in, v_in, Wq, Wk, Wv, bq, bk, bv);
    k_vsum<<<32, 256>>>();
    k_attn<<<dim3(16, 32), 512, SM_A>>>(dattn, use_dout);
    k_out<<<dim3(8, 32), 256, SM_G>>>(Wo, bo, out);
}

// round 9
// speedup vs baseline: 1.0786x; 1.0786x over previous
#include <cuda_runtime.h>
#include <cstdint>
#include <cstddef>

// MHA forward: B=2, S=2048, D_MODEL=1024, H=16, DK=64
// Outputs: out [2,2048,1024] then attn [2,16,2048,2048] (fp32, concatenated).
// tf32 mma.sync; q/k/v pre-rounded to tf32 at projection epilogue.
// k_attn: single pass, raw (unnormalized) e written to attn + rinv to gmem.
// k_scale: separate high-occupancy streaming kernel normalizes attn in place.

#define QK_SCALE 0.125f
#define UNIF 0.00048828125f   // 1/2048, exact power of two

// ---------------- device scratch ----------------
__device__ __align__(256) float g_q[2 * 16 * 2048 * 64];
__device__ __align__(256) float g_k[2 * 16 * 2048 * 64];
__device__ __align__(256) float g_v[2 * 16 * 2048 * 64];
__device__ __align__(256) float g_ctx[4096 * 1024];
__device__ __align__(256) float g_vsum[32 * 64];     // per (b,h): colsum of V
__device__ __align__(256) float g_rinv[32 * 2048];   // 1/rowsum; -1 => uniform row
__device__ __align__(256) unsigned char g_mask[4096];
__device__ __align__(256) float g_attn[134217728];   // fallback

// ---------------- helpers ----------------
__device__ __forceinline__ float t32(float x) {
    unsigned u;
    asm("cvt.rna.tf32.f32 %0, %1;" : "=r"(u) : "f"(x));
    return __uint_as_float(u);
}

__device__ __forceinline__ void mma8(float c[4], const unsigned a[4], const unsigned b[2]) {
    asm volatile("mma.sync.aligned.m16n8k8.row.col.f32.tf32.tf32.f32 "
                 "{%0,%1,%2,%3},{%4,%5,%6,%7},{%8,%9},{%0,%1,%2,%3};"
                 : "+f"(c[0]), "+f"(c[1]), "+f"(c[2]), "+f"(c[3])
                 : "r"(a[0]), "r"(a[1]), "r"(a[2]), "r"(a[3]),
                   "r"(b[0]), "r"(b[1]));
}

__device__ __forceinline__ unsigned s2u(const void* p) {
    return (unsigned)__cvta_generic_to_shared(p);
}
__device__ __forceinline__ void cpa16(unsigned dst, const void* src) {
    asm volatile("cp.async.cg.shared.global [%0], [%1], 16;" :: "r"(dst), "l"(src));
}
__device__ __forceinline__ void cpa_commit() {
    asm volatile("cp.async.commit_group;" ::: "memory");
}
template<int N> __device__ __forceinline__ void cpa_wait() {
    asm volatile("cp.async.wait_group %0;" :: "n"(N) : "memory");
}

// copy 128x64-float tile (row stride 64 gmem) to smem (row stride 68), 512 thr
__device__ __forceinline__ void cp_tile512(float* dstbase, const float* src, int tid) {
#pragma unroll
    for (int j = 0; j < 4; j++) {
        const int i = tid + 512 * j;
        const int r = i >> 4, c = (i & 15) << 2;
        cpa16(s2u(dstbase + r * 68 + c), src + r * 64 + c);
    }
}

// ---------------- mask canonicalization + vsum zeroing ----------------
__global__ void k_mask(const unsigned int* __restrict__ raw)
{
    __shared__ int flags[4];
    __shared__ int mode;
    const int tid = threadIdx.x;
    if (tid < 4) flags[tid] = 0;
    g_vsum[tid] = 0.0f;
    g_vsum[tid + 1024] = 0.0f;
    __syncthreads();
    unsigned int w = raw[tid];
    if (w > 1u) flags[0] = 1;
    if (w == 1u) flags[1] = 1;
    if (w != 0u && w != 0x3F800000u) flags[2] = 1;
    if (w == 0x3F800000u) flags[3] = 1;
    __syncthreads();
    if (tid == 0) {
        if (!flags[0] && flags[1])      mode = 0;
        else if (!flags[2] && flags[3]) mode = 1;
        else                            mode = 2;
    }
    __syncthreads();
    const int md = mode;
    for (int i = tid; i < 4096; i += 1024) {
        unsigned char v;
        if (md == 0)      v = (unsigned char)(((const int*)raw)[i] != 0);
        else if (md == 1) v = (unsigned char)(((const float*)raw)[i] != 0.0f);
        else              v = (unsigned char)(((const unsigned char*)raw)[i] != 0);
        g_mask[i] = v;
    }
}

// ---------------- vsum: g_vsum[bh][d] += partial colsum of V --------------
// grid (32, 16), 256 threads; block sums 128 k-rows, atomicAdd per (bh,d).
__global__ void k_vsum()
{
    __shared__ float part[4][64];
    const int bh = blockIdx.x;
    const int d = threadIdx.x & 63, j = threadIdx.x >> 6;
    const float* Vp = g_v + (size_t)bh * 2048 * 64 + (size_t)blockIdx.y * 128 * 64;
    float s = 0.0f;
    for (int k = j; k < 128; k += 4) s += Vp[(size_t)k * 64 + d];
    part[j][d] = s;
    __syncthreads();
    if (threadIdx.x < 64)
        atomicAdd(&g_vsum[bh * 64 + threadIdx.x],
                  part[0][threadIdx.x] + part[1][threadIdx.x]
                + part[2][threadIdx.x] + part[3][threadIdx.x]);
}

// ============ GEMM core: C = A @ W^T + bias, M=4096,N=1024,K=1024 ========
extern __shared__ float smem_dyn[];

template<int ROUND_SCATTER>
__device__ __forceinline__ void gemm_body(
    const float* __restrict__ A, const float* __restrict__ W,
    const float* __restrict__ bias, float* __restrict__ tgt)
{
    const int tid = threadIdx.x;
    const int bm = blockIdx.y * 128;
    const int bn = blockIdx.x * 128;
    const int w = tid >> 5, lane = tid & 31;
    const int g = lane >> 2, t = lane & 3;
    const int wm = (w >> 2) * 64, wn = (w & 3) * 32;
    const int lr = tid >> 1, lk = (tid & 1) * 8;
    const float* Ap = A + (size_t)(bm + lr) * 1024 + lk;
    const float* Wp = W + (size_t)(bn + lr) * 1024 + lk;

    float acc[4][4][4];
#pragma unroll
    for (int mt = 0; mt < 4; mt++)
#pragma unroll
        for (int nt = 0; nt < 4; nt++)
#pragma unroll
            for (int i = 0; i < 4; i++) acc[mt][nt][i] = 0.0f;

    float4 ra0, ra1, rw0, rw1;
    ra0 = *(const float4*)(Ap);     ra1 = *(const float4*)(Ap + 4);
    rw0 = *(const float4*)(Wp);     rw1 = *(const float4*)(Wp + 4);
    {
        float* pa = smem_dyn + lr * 20 + lk;
        float* pw = smem_dyn + 5120 + lr * 20 + lk;
        float4 ta = make_float4(t32(ra0.x), t32(ra0.y), t32(ra0.z), t32(ra0.w));
        float4 tb = make_float4(t32(ra1.x), t32(ra1.y), t32(ra1.z), t32(ra1.w));
        *(float4*)pa = ta; *(float4*)(pa + 4) = tb;
        ta = make_float4(t32(rw0.x), t32(rw0.y), t32(rw0.z), t32(rw0.w));
        tb = make_float4(t32(rw1.x), t32(rw1.y), t32(rw1.z), t32(rw1.w));
        *(float4*)pw = ta; *(float4*)(pw + 4) = tb;
    }
    __syncthreads();

    for (int kc = 0; kc < 64; kc++) {
        const int s = kc & 1;
        if (kc < 63) {
            const int off = (kc + 1) * 16;
            ra0 = *(const float4*)(Ap + off);     ra1 = *(const float4*)(Ap + off + 4);
            rw0 = *(const float4*)(Wp + off);     rw1 = *(const float4*)(Wp + off + 4);
        }
        const float* As = smem_dyn + s * 2560;
        const float* Ws = smem_dyn + 5120 + s * 2560;
#pragma unroll
        for (int kk = 0; kk < 2; kk++) {
            unsigned af[4][4], bf[4][2];
#pragma unroll
            for (int mt = 0; mt < 4; mt++) {
                const float* p = As + (wm + mt * 16 + g) * 20 + kk * 8 + t;
                af[mt][0] = __float_as_uint(p[0]);
                af[mt][1] = __float_as_uint(p[8 * 20]);
                af[mt][2] = __float_as_uint(p[4]);
                af[mt][3] = __float_as_uint(p[8 * 20 + 4]);
            }
#pragma unroll
            for (int nt = 0; nt < 4; nt++) {
                const float* p = Ws + (wn + nt * 8 + g) * 20 + kk * 8 + t;
                bf[nt][0] = __float_as_uint(p[0]);
                bf[nt][1] = __float_as_uint(p[4]);
            }
#pragma unroll
            for (int mt = 0; mt < 4; mt++)
#pragma unroll
                for (int nt = 0; nt < 4; nt++)
                    mma8(acc[mt][nt], af[mt], bf[nt]);
        }
        if (kc < 63) {
            const int s2 = (kc + 1) & 1;
            float* pa = smem_dyn + s2 * 2560 + lr * 20 + lk;
            float* pw = smem_dyn + 5120 + s2 * 2560 + lr * 20 + lk;
            float4 ta = make_float4(t32(ra0.x), t32(ra0.y), t32(ra0.z), t32(ra0.w));
            float4 tb = make_float4(t32(ra1.x), t32(ra1.y), t32(ra1.z), t32(ra1.w));
            *(float4*)pa = ta; *(float4*)(pa + 4) = tb;
            ta = make_float4(t32(rw0.x), t32(rw0.y), t32(rw0.z), t32(rw0.w));
            tb = make_float4(t32(rw1.x), t32(rw1.y), t32(rw1.z), t32(rw1.w));
            *(float4*)pw = ta; *(float4*)(pw + 4) = tb;
        }
        __syncthreads();
    }

#pragma unroll
    for (int mt = 0; mt < 4; mt++) {
#pragma unroll
        for (int nt = 0; nt < 4; nt++) {
            const int c0 = bn + wn + nt * 8 + 2 * t;
            const float b0v = bias[c0], b1v = bias[c0 + 1];
#pragma unroll
            for (int half = 0; half < 2; half++) {
                const int m = bm + wm + mt * 16 + g + half * 8;
                float v0 = acc[mt][nt][half * 2 + 0] + b0v;
                float v1 = acc[mt][nt][half * 2 + 1] + b1v;
                if (ROUND_SCATTER) {
                    v0 = t32(v0); v1 = t32(v1);
                    const int b = m >> 11, sr = m & 2047;
                    const int h = c0 >> 6, d = c0 & 63;
                    float* dst = tgt + (((size_t)((b << 4) + h)) * 2048 + sr) * 64 + d;
                    dst[0] = v0; dst[1] = v1;
                } else {
                    float* dst = tgt + (size_t)m * 1024 + c0;
                    dst[0] = v0; dst[1] = v1;
                }
            }
        }
    }
}

__global__ __launch_bounds__(256, 2) void k_proj(
    const float* __restrict__ A0, const float* __restrict__ A1, const float* __restrict__ A2,
    const float* __restrict__ W0, const float* __restrict__ W1, const float* __restrict__ W2,
    const float* __restrict__ b0, const float* __restrict__ b1, const float* __restrict__ b2)
{
    const int z = blockIdx.z;
    const float* A = (z == 0) ? A0 : (z == 1) ? A1 : A2;
    const float* W = (z == 0) ? W0 : (z == 1) ? W1 : W2;
    const float* b = (z == 0) ? b0 : (z == 1) ? b1 : b2;
    float* tgt = (z == 0) ? g_q : (z == 1) ? g_k : g_v;
    gemm_body<1>(A, W, b, tgt);
}

__global__ __launch_bounds__(256, 2) void k_out(
    const float* __restrict__ W, const float* __restrict__ b, float* __restrict__ out)
{
    gemm_body<0>(g_ctx, W, b, out);
}

// ============ fused attention core, single pass, 512 threads =============
// smem float layout:
//  Qs 0 (8704), Ks[2] 8704/17408, Vs 26112 (8704), Ps 34816 (16896 = 128x132),
//  rowsum 51712, rinv 51840, runi 51968(int), Ms @ float 52096 (2048 B)
__global__ __launch_bounds__(512) void k_attn(float* __restrict__ dattn, int use_dout)
{
    float* Qs = smem_dyn;
    float* Vs = smem_dyn + 26112;
    float* Ps = smem_dyn + 34816;
    float* rowsum = smem_dyn + 51712;
    float* rinv   = smem_dyn + 51840;
    int*   runi   = (int*)(smem_dyn + 51968);
    unsigned char* Ms = (unsigned char*)(smem_dyn + 52096);

    float* attn = use_dout ? dattn : g_attn;
    const int tid = threadIdx.x;
    const int bh = blockIdx.y;
    const int bb = bh >> 4, hh = bh & 15;
    const int x = blockIdx.x;          // q-tile index
    const int q0 = x * 128;
    const float* Qp = g_q + (size_t)bh * 2048 * 64;
    const float* Kp = g_k + (size_t)bh * 2048 * 64;
    const float* Vp = g_v + (size_t)bh * 2048 * 64;

    const int w = tid >> 5, lane = tid & 31;
    const int g = lane >> 2, t = lane & 3;
    const int wmS = (w >> 2) * 32, wnS = (w & 3) * 32;   // scores 4x4, warp tile 32x32
    const int wmO = (w >> 1) * 16, wnO = (w & 1) * 32;   // PV 8x2, warp tile 16x32

    // ---- init + prologue (one group: Qs, Ks(0), mask) ----
    if (tid < 128) rowsum[tid] = 0.0f;
    cp_tile512(Qs, Qp + (size_t)q0 * 64, tid);
    cp_tile512(smem_dyn + 8704, Kp, tid);
    if (tid < 128)
        cpa16(s2u(Ms + tid * 16), g_mask + bb * 2048 + tid * 16);
    cpa_commit();

    float rs[2][2];
    rs[0][0] = rs[0][1] = rs[1][0] = rs[1][1] = 0.0f;
    float oacc[4][4];
#pragma unroll
    for (int nt = 0; nt < 4; nt++)
#pragma unroll
        for (int i = 0; i < 4; i++) oacc[nt][i] = 0.0f;

    // ---- single pass over live chunks ----
    for (int kc = 0; kc <= x; kc++) {
        const int kc0 = kc * 128;
        cpa_wait<0>();            // Ks(kc) ready (drains all pending)
        __syncthreads();          // prior Vs/Ps consumers done
        cp_tile512(Vs, Vp + (size_t)kc0 * 64, tid);
        cpa_commit();             // group A (Vs)
        if (kc < x) {
            cp_tile512(smem_dyn + 8704 + ((kc + 1) & 1) * 8704,
                       Kp + (size_t)(kc + 1) * 128 * 64, tid);
        }
        cpa_commit();             // group B — always committed (may be empty)
        const float* Kb = smem_dyn + 8704 + (kc & 1) * 8704;

        // QK mma
        float acc[2][4][4];
#pragma unroll
        for (int mt = 0; mt < 2; mt++)
#pragma unroll
            for (int nt = 0; nt < 4; nt++)
#pragma unroll
                for (int i = 0; i < 4; i++) acc[mt][nt][i] = 0.0f;
#pragma unroll
        for (int kk = 0; kk < 8; kk++) {
            unsigned af[2][4], bf[4][2];
#pragma unroll
            for (int mt = 0; mt < 2; mt++) {
                const float* p = Qs + (wmS + mt * 16 + g) * 68 + kk * 8 + t;
                af[mt][0] = __float_as_uint(p[0]);
                af[mt][1] = __float_as_uint(p[8 * 68]);
                af[mt][2] = __float_as_uint(p[4]);
                af[mt][3] = __float_as_uint(p[8 * 68 + 4]);
            }
#pragma unroll
            for (int nt = 0; nt < 4; nt++) {
                const float* p = Kb + (wnS + nt * 8 + g) * 68 + kk * 8 + t;
                bf[nt][0] = __float_as_uint(p[0]);
                bf[nt][1] = __float_as_uint(p[4]);
            }
#pragma unroll
            for (int mt = 0; mt < 2; mt++)
#pragma unroll
                for (int nt = 0; nt < 4; nt++)
                    mma8(acc[mt][nt], af[mt], bf[nt]);
        }

        // epilogue: e = exp(masked s) (UNNORMALIZED); rowsum accumulate; Ps <- e
#pragma unroll
        for (int mt = 0; mt < 2; mt++) {
#pragma unroll
            for (int half = 0; half < 2; half++) {
                const int rl = wmS + mt * 16 + g + 8 * half;
                const int rq = q0 + rl;
#pragma unroll
                for (int nt = 0; nt < 4; nt++) {
                    const int cl = wnS + nt * 8 + 2 * t;
                    const int c0 = kc0 + cl;
                    const unsigned char mk0 = Ms[c0], mk1 = Ms[c0 + 1];
                    const float s0 = acc[mt][nt][half*2+0] * QK_SCALE;
                    const float s1 = acc[mt][nt][half*2+1] * QK_SCALE;
                    float e0 = (!mk0 || c0 > rq)     ? 0.0f : __expf(s0);
                    float e1 = (!mk1 || c0 + 1 > rq) ? 0.0f : __expf(s1);
                    rs[mt][half] += e0 + e1;
                    *(float2*)(Ps + rl * 132 + cl) = make_float2(e0, e1);
                }
            }
        }
        cpa_wait<1>();            // drain group A (Vs); group B (next Ks) may pend
        __syncthreads();          // Ps + Vs visible to all

        // write RAW e to attn (coalesced); k_scale normalizes later
#pragma unroll
        for (int u = 0; u < 8; u++) {
            const int f = tid + 512 * u;
            const int r = f >> 5, c = (f & 31) * 4;
            float4 v = *(const float4*)(Ps + r * 132 + c);
            *(float4*)(attn + ((size_t)(bh * 2048 + q0 + r)) * 2048 + kc0 + c) = v;
        }

        // PV mma with unnormalized e: oacc += t32(Ps) @ Vs  (warp tile 16x32)
#pragma unroll
        for (int kk = 0; kk < 16; kk++) {
            unsigned af[4], bf[4][2];
            {
                const float* p = Ps + (wmO + g) * 132 + kk * 8 + t;
                af[0] = __float_as_uint(t32(p[0]));
                af[1] = __float_as_uint(t32(p[8 * 132]));
                af[2] = __float_as_uint(t32(p[4]));
                af[3] = __float_as_uint(t32(p[8 * 132 + 4]));
            }
#pragma unroll
            for (int nt = 0; nt < 4; nt++) {
                const float* p = Vs + (kk * 8 + t) * 68 + wnO + nt * 8 + g;
                bf[nt][0] = __float_as_uint(p[0]);
                bf[nt][1] = __float_as_uint(p[4 * 68]);
            }
#pragma unroll
            for (int nt = 0; nt < 4; nt++)
                mma8(oacc[nt], af, bf[nt]);
        }
    }

    // ---- rowsum reduce -> rinv / runi, store g_rinv ----
#pragma unroll
    for (int mt = 0; mt < 2; mt++)
#pragma unroll
        for (int half = 0; half < 2; half++) {
            float v = rs[mt][half];
            v += __shfl_xor_sync(0xffffffffu, v, 1);
            v += __shfl_xor_sync(0xffffffffu, v, 2);
            if (t == 0) atomicAdd(&rowsum[wmS + mt * 16 + g + 8 * half], v);
        }
    __syncthreads();
    if (tid < 128) {
        const float s = rowsum[tid];
        float ri;
        if (s == 0.0f) { runi[tid] = 1; ri = 0.0f; g_rinv[bh * 2048 + q0 + tid] = -1.0f; }
        else           { runi[tid] = 0; ri = 1.0f / s; g_rinv[bh * 2048 + q0 + tid] = ri; }
        rinv[tid] = ri;
    }
    __syncthreads();

    // ---- finalize oacc: scale by rinv; uniform rows -> UNIF * vsum ----
#pragma unroll
    for (int nt = 0; nt < 4; nt++) {
        const int d0 = wnO + nt * 8 + 2 * t;
#pragma unroll
        for (int half = 0; half < 2; half++) {
            const int rl = wmO + g + half * 8;
            const int rq = q0 + rl;
            float v0, v1;
            if (runi[rl]) {
                v0 = UNIF * g_vsum[bh * 64 + d0];
                v1 = UNIF * g_vsum[bh * 64 + d0 + 1];
            } else {
                const float ri = rinv[rl];
                v0 = oacc[nt][half*2+0] * ri;
                v1 = oacc[nt][half*2+1] * ri;
            }
            *(float2*)(g_ctx + ((size_t)(bb * 2048 + rq)) * 1024 + hh * 64 + d0)
                = make_float2(v0, v1);
        }
    }
}

// ============ scale kernel: normalize attn in place, fill dead region ====
// grid (128, 32), 512 threads, no smem -> 4 blocks/SM, saturates HBM.
__global__ __launch_bounds__(512) void k_scale(float* __restrict__ dattn, int use_dout)
{
    float* attn = use_dout ? dattn : g_attn;
    const int bh = blockIdx.y;
    const int q = blockIdx.x * 16 + (threadIdx.x >> 5);
    const int lane = threadIdx.x & 31;
    const float ri = g_rinv[bh * 2048 + q];
    float* row = attn + ((size_t)(bh * 2048 + q)) * 2048;
    const int lim = ((q >> 7) + 1) << 7;   // live cols: [0, lim)

    if (ri < 0.0f) {
        const float4 uv = make_float4(UNIF, UNIF, UNIF, UNIF);
#pragma unroll 4
        for (int c = lane * 4; c < 2048; c += 128)
            *(float4*)(row + c) = uv;
    } else {
#pragma unroll 4
        for (int c = lane * 4; c < 2048; c += 128) {
            float4 v;
            if (c < lim) {
                v = *(const float4*)(row + c);
                v.x *= ri; v.y *= ri; v.z *= ri; v.w *= ri;
            } else {
                v = make_float4(0.f, 0.f, 0.f, 0.f);
            }
            *(float4*)(row + c) = v;
        }
    }
}

// ---------------- launch ----------------
extern "C" void kernel_launch(void* const* d_in, const int* in_sizes, int n_in,
                              void* d_out, int out_size)
{
    const float* q_in = (const float*)d_in[0];
    const float* k_in = (const float*)d_in[1];
    const float* v_in = (const float*)d_in[2];
    const void*  mask = d_in[3];
    const float* Wq = (const float*)d_in[4];  const float* bq = (const float*)d_in[5];
    const float* Wk = (const float*)d_in[6];  const float* bk = (const float*)d_in[7];
    const float* Wv = (const float*)d_in[8];  const float* bv = (const float*)d_in[9];
    const float* Wo = (const float*)d_in[10]; const float* bo = (const float*)d_in[11];
    float* out = (float*)d_out;

    const int use_dout = (out_size >= 4194304 + 134217728) ? 1 : 0;
    float* dattn = out + 4194304;

    const int SM_G = 10240 * 4;               // 40 KB
    const int SM_A = (52100 + 512) * 4;       // ~205.5 KB
    cudaFuncSetAttribute(k_proj, cudaFuncAttributeMaxDynamicSharedMemorySize, SM_G);
    cudaFuncSetAttribute(k_out,  cudaFuncAttributeMaxDynamicSharedMemorySize, SM_G);
    cudaFuncSetAttribute(k_attn, cudaFuncAttributeMaxDynamicSharedMemorySize, SM_A);

    k_mask<<<1, 1024>>>((const unsigned int*)mask);

    k_proj<<<dim3(8, 32, 3), 256, SM_G>>>(q_in, k_in, v_in, Wq, Wk, Wv, bq, bk, bv);
    k_vsum<<<dim3(32, 16), 256>>>();
    k_attn<<<dim3(16, 32), 512, SM_A>>>(dattn, use_dout);
    k_scale<<<dim3(128, 32), 512>>>(dattn, use_dout);
    k_out<<<dim3(8, 32), 256, SM_G>>>(Wo, bo, out);
}